// round 16
// baseline (speedup 1.0000x reference)
#include <cuda_runtime.h>
#include <cuda_bf16.h>
#include <math.h>
#include <stdint.h>

typedef __nv_bfloat16 bf16;

// ---------------- problem constants ----------------
#define TS   63
#define BB   256
#define OBSD 512
#define ACTD 32
#define EMBD 1024
#define DETD 1024
#define STOD 256
#define RR   (TS*BB)
#define FEATD (DETD+STOD)   // 1280
#define SN   4096           // S width: [prior 512 | post 512 | gh 3072]
#define KIH  320            // padded gzgru K: [z 256 | a 32 | pad 32]

// ---------------- device scratch ----------------
__device__ bf16  g_obsb[RR*OBSD];
__device__ bf16  g_embh[RR*EMBD];
__device__ bf16  g_emb [RR*EMBD];
__device__ float g_post_emb[RR*512];
__device__ bf16  g_feat[RR*FEATD];          // [h | z]
__device__ bf16  g_H1  [RR*2048];
__device__ float g_pred[RR*OBSD];
__device__ float g_S_all[(size_t)RR*SN];
__device__ bf16  g_h[BB*DETD];
__device__ float g_kl[RR];
__device__ float g_recon[RR];
__device__ float g_rewl[RR];
__device__ unsigned g_bar;                  // phase-B barrier (monotonic per run)
// weights (bf16), pre-transposed to [N,K]
__device__ bf16  g_WhT[SN*DETD];            // [prior | post_h | whh^T]
__device__ float g_bh[SN];
__device__ bf16  g_wihP[3*DETD*KIH];        // padded [3072, 320]
__device__ bf16  g_encw1T[EMBD*OBSD];
__device__ bf16  g_encw2T[EMBD*EMBD];
__device__ bf16  g_postEmbT[512*EMBD];
__device__ bf16  g_decw2T[OBSD*EMBD];
__device__ bf16  g_W1fT[2048*FEATD];
__device__ float g_b1f[2048];

__device__ __forceinline__ uint32_t pack_bf2(float a, float b) {
    __nv_bfloat162 h = __floats2bfloat162_rn(a, b);
    return *(uint32_t*)&h;
}
__device__ __forceinline__ int swz(int r, int k) {   // k = uint32 col 0..31
    return r*32 + (k ^ ((r & 7) << 2));
}
__device__ __forceinline__ void cp16(uint32_t saddr, const void* g) {
    asm volatile("cp.async.cg.shared.global [%0], [%1], 16;" :: "r"(saddr), "l"(g));
}
__device__ __forceinline__ void cp_commit() {
    asm volatile("cp.async.commit_group;" ::: "memory");
}
template<int N> __device__ __forceinline__ void cp_wait() {
    asm volatile("cp.async.wait_group %0;" :: "n"(N) : "memory");
}
#define MMA_BF16(c, a, b) \
    asm volatile( \
        "mma.sync.aligned.m16n8k16.row.col.f32.bf16.bf16.f32 " \
        "{%0,%1,%2,%3}, {%4,%5,%6,%7}, {%8,%9}, {%0,%1,%2,%3};" \
        : "+f"((c)[0]), "+f"((c)[1]), "+f"((c)[2]), "+f"((c)[3]) \
        : "r"((a)[0]), "r"((a)[1]), "r"((a)[2]), "r"((a)[3]), \
          "r"((b)[0]), "r"((b)[1]))

// ================= cp.async double-buffered bf16 GEMM (Phases A/C) =================
template<int BM>
__global__ void __launch_bounds__(256) ca_gemm(
    const bf16* __restrict__ A, int lda,
    const bf16* __restrict__ B, int ldb,
    void* __restrict__ Cv, int ldc,
    const float* __restrict__ bias, int K, int relu, int outbf)
{
    extern __shared__ uint32_t smem[];
    uint32_t* As = smem;               // 2 * BM*32
    uint32_t* Bs = smem + 2*BM*32;     // 2 * 128*32

    const int tid = threadIdx.x;
    const int wid = tid >> 5, lane = tid & 31;
    constexpr int WM   = BM/32;
    constexpr int WN   = 8/WM;
    constexpr int NCOL = 128/WN;
    constexpr int NAT  = NCOL/8;
    const int warp_m = wid % WM;
    const int warp_n = wid / WM;
    const int gid = lane >> 2, tig = lane & 3;
    const long brow = (long)blockIdx.y * BM;
    const long bcol = (long)blockIdx.x * 128;
    const int nch = K >> 6;

    const uint32_t as_u = (uint32_t)__cvta_generic_to_shared(As);
    const uint32_t bs_u = (uint32_t)__cvta_generic_to_shared(Bs);

    float c[2][NAT][4];
    #pragma unroll
    for (int im = 0; im < 2; im++)
        #pragma unroll
        for (int in_ = 0; in_ < NAT; in_++)
            #pragma unroll
            for (int j = 0; j < 4; j++) c[im][in_][j] = 0.0f;

    constexpr int NA = BM/32;
    int fr[NA], fkc[NA];
    #pragma unroll
    for (int i = 0; i < NA; i++) {
        int lin = i*256 + tid;
        fr[i]  = lin >> 3;
        fkc[i] = (lin & 7) << 2;
    }
    int gr[4], gkc[4];
    #pragma unroll
    for (int i = 0; i < 4; i++) {
        int lin = i*256 + tid;
        gr[i]  = lin >> 3;
        gkc[i] = (lin & 7) << 2;
    }

    #define CA_ISSUE(cc)                                                           \
    do {                                                                           \
        int k0 = (cc) << 6; int buf = (cc) & 1;                                    \
        _Pragma("unroll")                                                          \
        for (int i = 0; i < NA; i++)                                               \
            cp16(as_u + (uint32_t)(buf*BM*32 + swz(fr[i], fkc[i]))*4,              \
                 A + (brow + fr[i])*(long)lda + k0 + fkc[i]*2);                    \
        _Pragma("unroll")                                                          \
        for (int i = 0; i < 4; i++)                                                \
            cp16(bs_u + (uint32_t)(buf*128*32 + swz(gr[i], gkc[i]))*4,             \
                 B + (bcol + gr[i])*(long)ldb + k0 + gkc[i]*2);                    \
        cp_commit();                                                               \
    } while (0)

    CA_ISSUE(0);

    for (int cch = 0; cch < nch; cch++) {
        if (cch + 1 < nch) { CA_ISSUE(cch + 1); cp_wait<1>(); }
        else               { cp_wait<0>(); }
        __syncthreads();

        const uint32_t* Ap = As + (cch & 1)*BM*32;
        const uint32_t* Bp = Bs + (cch & 1)*128*32;

        #pragma unroll
        for (int kb = 0; kb < 4; kb++) {
            const int kk = kb*8 + tig;
            uint32_t af[2][4];
            #pragma unroll
            for (int ia = 0; ia < 2; ia++) {
                int m0 = warp_m*32 + ia*16 + gid;
                int x  = (m0 & 7) << 2;
                af[ia][0] = Ap[m0*32     + (kk     ^ x)];
                af[ia][1] = Ap[(m0+8)*32 + (kk     ^ x)];
                af[ia][2] = Ap[m0*32     + ((kk+4) ^ x)];
                af[ia][3] = Ap[(m0+8)*32 + ((kk+4) ^ x)];
            }
            uint32_t bf[NAT][2];
            #pragma unroll
            for (int nb = 0; nb < NAT; nb++) {
                int n = warp_n*NCOL + nb*8 + gid;
                int x = (n & 7) << 2;
                bf[nb][0] = Bp[n*32 + (kk     ^ x)];
                bf[nb][1] = Bp[n*32 + ((kk+4) ^ x)];
            }
            #pragma unroll
            for (int im = 0; im < 2; im++)
                #pragma unroll
                for (int in_ = 0; in_ < NAT; in_++)
                    MMA_BF16(c[im][in_], af[im], bf[in_]);
        }
        __syncthreads();
    }
    #undef CA_ISSUE

    #pragma unroll
    for (int im = 0; im < 2; im++) {
        long r0 = brow + warp_m*32 + im*16 + gid;
        #pragma unroll
        for (int in_ = 0; in_ < NAT; in_++) {
            long cb = bcol + warp_n*NCOL + in_*8 + tig*2;
            #pragma unroll
            for (int half = 0; half < 2; half++) {
                long row = r0 + half*8;
                float v0 = c[im][in_][half*2 + 0];
                float v1 = c[im][in_][half*2 + 1];
                if (bias) { v0 += bias[cb]; v1 += bias[cb + 1]; }
                if (relu) { v0 = fmaxf(v0, 0.f); v1 = fmaxf(v1, 0.f); }
                if (outbf) {
                    *(uint32_t*)((bf16*)Cv + row*(long)ldc + cb) = pack_bf2(v0, v1);
                } else {
                    *(float2*)((float*)Cv + row*(long)ldc + cb) = make_float2(v0, v1);
                }
            }
        }
    }
}

// ================= fused Phase B step kernel =================
// grid = 128 CTAs. Phase 1: S tile (bx=bid&31, by=bid>>5), BM=64.
// Barrier. Phase 2: CTAs 0..63 do gzgru tiles (nb=bid&7, brow=(bid>>3)*32).

// --- device S-GEMM tile (ca_gemm<64> body) ---
__device__ __forceinline__ void dev_sgemm64(
    uint32_t* smem, int bx, int by,
    const bf16* __restrict__ A,
    const bf16* __restrict__ B,
    float* __restrict__ C,
    const float* __restrict__ bias)
{
    uint32_t* As = smem;               // 2*64*32
    uint32_t* Bs = smem + 2*64*32;     // 2*128*32
    const int tid = threadIdx.x;
    const int wid = tid >> 5, lane = tid & 31;
    const int warp_m = wid & 1;        // WM=2
    const int warp_n = wid >> 1;       // WN=4, NCOL=32, NAT=4
    const int gid = lane >> 2, tig = lane & 3;
    const long brow = (long)by * 64;
    const long bcol = (long)bx * 128;
    const int nch = DETD >> 6;         // 16

    const uint32_t as_u = (uint32_t)__cvta_generic_to_shared(As);
    const uint32_t bs_u = (uint32_t)__cvta_generic_to_shared(Bs);

    float c[2][4][4];
    #pragma unroll
    for (int im = 0; im < 2; im++)
        #pragma unroll
        for (int in_ = 0; in_ < 4; in_++)
            #pragma unroll
            for (int j = 0; j < 4; j++) c[im][in_][j] = 0.0f;

    int fr[2], fkc[2];
    #pragma unroll
    for (int i = 0; i < 2; i++) {
        int lin = i*256 + tid;
        fr[i]  = lin >> 3;
        fkc[i] = (lin & 7) << 2;
    }
    int gr[4], gkc[4];
    #pragma unroll
    for (int i = 0; i < 4; i++) {
        int lin = i*256 + tid;
        gr[i]  = lin >> 3;
        gkc[i] = (lin & 7) << 2;
    }

    #define SG_ISSUE(cc)                                                           \
    do {                                                                           \
        int k0 = (cc) << 6; int buf = (cc) & 1;                                    \
        _Pragma("unroll")                                                          \
        for (int i = 0; i < 2; i++)                                                \
            cp16(as_u + (uint32_t)(buf*64*32 + swz(fr[i], fkc[i]))*4,              \
                 A + (brow + fr[i])*(long)DETD + k0 + fkc[i]*2);                   \
        _Pragma("unroll")                                                          \
        for (int i = 0; i < 4; i++)                                                \
            cp16(bs_u + (uint32_t)(buf*128*32 + swz(gr[i], gkc[i]))*4,             \
                 B + (bcol + gr[i])*(long)DETD + k0 + gkc[i]*2);                   \
        cp_commit();                                                               \
    } while (0)

    SG_ISSUE(0);

    for (int cch = 0; cch < nch; cch++) {
        if (cch + 1 < nch) { SG_ISSUE(cch + 1); cp_wait<1>(); }
        else               { cp_wait<0>(); }
        __syncthreads();

        const uint32_t* Ap = As + (cch & 1)*64*32;
        const uint32_t* Bp = Bs + (cch & 1)*128*32;

        #pragma unroll
        for (int kb = 0; kb < 4; kb++) {
            const int kk = kb*8 + tig;
            uint32_t af[2][4];
            #pragma unroll
            for (int ia = 0; ia < 2; ia++) {
                int m0 = warp_m*32 + ia*16 + gid;
                int x  = (m0 & 7) << 2;
                af[ia][0] = Ap[m0*32     + (kk     ^ x)];
                af[ia][1] = Ap[(m0+8)*32 + (kk     ^ x)];
                af[ia][2] = Ap[m0*32     + ((kk+4) ^ x)];
                af[ia][3] = Ap[(m0+8)*32 + ((kk+4) ^ x)];
            }
            uint32_t bfr[4][2];
            #pragma unroll
            for (int nb = 0; nb < 4; nb++) {
                int n = warp_n*32 + nb*8 + gid;
                int x = (n & 7) << 2;
                bfr[nb][0] = Bp[n*32 + (kk     ^ x)];
                bfr[nb][1] = Bp[n*32 + ((kk+4) ^ x)];
            }
            #pragma unroll
            for (int im = 0; im < 2; im++)
                #pragma unroll
                for (int in_ = 0; in_ < 4; in_++)
                    MMA_BF16(c[im][in_], af[im], bfr[in_]);
        }
        __syncthreads();
    }
    #undef SG_ISSUE

    #pragma unroll
    for (int im = 0; im < 2; im++) {
        long r0 = brow + warp_m*32 + im*16 + gid;
        #pragma unroll
        for (int in_ = 0; in_ < 4; in_++) {
            long cb = bcol + warp_n*32 + in_*8 + tig*2;
            #pragma unroll
            for (int half = 0; half < 2; half++) {
                long row = r0 + half*8;
                float v0 = c[im][in_][half*2 + 0] + bias[cb];
                float v1 = c[im][in_][half*2 + 1] + bias[cb + 1];
                *(float2*)(C + row*(long)SN + cb) = make_float2(v0, v1);
            }
        }
    }
}

// --- device gzgru tile (R12 gzgru_k body) ---
__device__ __forceinline__ void dev_gz(
    uint32_t* smem, int nb, int brow,
    const float* __restrict__ S,
    const float* __restrict__ pe,
    const float* __restrict__ epst,
    const float* __restrict__ act,
    const bf16*  __restrict__ wihP,
    const float* __restrict__ bih,
    const unsigned char* __restrict__ dn,
    bf16* __restrict__ feat_t)
{
    uint32_t* As = smem;                  // 1024 u32
    uint32_t* Bs = smem + 1024;           // 2*12288 u32
    float* Gsm = (float*)smem;            // alias post-GEMM

    const int tid = threadIdx.x;
    const int wid = tid >> 5, lane = tid & 31;
    const int gid = lane >> 2, tig = lane & 3;
    const int nch = 5;                    // K = 320

    const uint32_t bs_u = (uint32_t)__cvta_generic_to_shared(Bs);

    float c[2][6][4];
    #pragma unroll
    for (int im = 0; im < 2; im++)
        #pragma unroll
        for (int in_ = 0; in_ < 6; in_++)
            #pragma unroll
            for (int j = 0; j < 4; j++) c[im][in_][j] = 0.0f;

    const int fr = tid >> 3, fkc = (tid & 7) << 2;
    int gr[12], gkc[12];
    #pragma unroll
    for (int i = 0; i < 12; i++) {
        int lin = i*256 + tid;
        gr[i]  = lin >> 3;
        gkc[i] = (lin & 7) << 2;
    }

    #define GZ_ISSUE_B(cc)                                                         \
    do {                                                                           \
        int k0 = (cc) << 6; int buf = (cc) & 1;                                    \
        _Pragma("unroll")                                                          \
        for (int i = 0; i < 12; i++) {                                             \
            int grow = (gr[i] >> 7)*1024 + nb*128 + (gr[i] & 127);                 \
            cp16(bs_u + (uint32_t)(buf*12288 + swz(gr[i], gkc[i]))*4,              \
                 wihP + (long)grow*KIH + k0 + gkc[i]*2);                           \
        }                                                                          \
        cp_commit();                                                               \
    } while (0)

    uint4 sA;
    #define GZ_LOAD_A(cc)                                                          \
    do {                                                                           \
        int j = ((cc) << 6) + (fkc << 1);                                          \
        int b = brow + fr;                                                         \
        if (j < 256) {                                                             \
            uint32_t pk[4];                                                        \
            _Pragma("unroll")                                                      \
            for (int q = 0; q < 2; q++) {                                          \
                int jj = j + q*4;                                                  \
                float4 qm = *(const float4*)(S + (long)b*SN + 512 + jj);           \
                float4 p1 = *(const float4*)(pe + (long)b*512 + jj);               \
                float4 ql = *(const float4*)(S + (long)b*SN + 768 + jj);           \
                float4 p2 = *(const float4*)(pe + (long)b*512 + 256 + jj);         \
                float4 e  = *(const float4*)(epst + (long)b*256 + jj);             \
                float z0 = (qm.x + p1.x) + e.x * expf(ql.x + p2.x);                \
                float z1 = (qm.y + p1.y) + e.y * expf(ql.y + p2.y);                \
                float z2 = (qm.z + p1.z) + e.z * expf(ql.z + p2.z);                \
                float z3 = (qm.w + p1.w) + e.w * expf(ql.w + p2.w);                \
                pk[q*2]   = pack_bf2(z0, z1);                                      \
                pk[q*2+1] = pack_bf2(z2, z3);                                      \
            }                                                                      \
            sA = make_uint4(pk[0], pk[1], pk[2], pk[3]);                           \
            if (nb == 0) *(uint4*)(feat_t + (long)b*FEATD + DETD + j) = sA;        \
        } else if (j < 288) {                                                      \
            float4 a0 = *(const float4*)(act + (long)b*ACTD + (j - 256));          \
            float4 a1 = *(const float4*)(act + (long)b*ACTD + (j - 256) + 4);      \
            sA = make_uint4(pack_bf2(a0.x, a0.y), pack_bf2(a0.z, a0.w),            \
                            pack_bf2(a1.x, a1.y), pack_bf2(a1.z, a1.w));           \
        } else {                                                                   \
            sA = make_uint4(0, 0, 0, 0);                                           \
        }                                                                          \
    } while (0)

    GZ_ISSUE_B(0);
    GZ_LOAD_A(0);

    for (int cch = 0; cch < nch; cch++) {
        __syncthreads();
        *(uint4*)&As[swz(fr, fkc)] = sA;
        if (cch + 1 < nch) { GZ_ISSUE_B(cch + 1); cp_wait<1>(); }
        else               { cp_wait<0>(); }
        __syncthreads();
        if (cch + 1 < nch) GZ_LOAD_A(cch + 1);

        const uint32_t* Ap = As;
        const uint32_t* Bp = Bs + (cch & 1)*12288;

        #pragma unroll
        for (int kb = 0; kb < 4; kb++) {
            const int kk = kb*8 + tig;
            uint32_t af[2][4];
            #pragma unroll
            for (int ia = 0; ia < 2; ia++) {
                int m0 = ia*16 + gid;
                int x  = (m0 & 7) << 2;
                af[ia][0] = Ap[m0*32     + (kk     ^ x)];
                af[ia][1] = Ap[(m0+8)*32 + (kk     ^ x)];
                af[ia][2] = Ap[m0*32     + ((kk+4) ^ x)];
                af[ia][3] = Ap[(m0+8)*32 + ((kk+4) ^ x)];
            }
            uint32_t bfr[6][2];
            #pragma unroll
            for (int nbi = 0; nbi < 6; nbi++) {
                int n = wid*48 + nbi*8 + gid;
                int x = (n & 7) << 2;
                bfr[nbi][0] = Bp[n*32 + (kk     ^ x)];
                bfr[nbi][1] = Bp[n*32 + ((kk+4) ^ x)];
            }
            #pragma unroll
            for (int im = 0; im < 2; im++)
                #pragma unroll
                for (int in_ = 0; in_ < 6; in_++)
                    MMA_BF16(c[im][in_], af[im], bfr[in_]);
        }
    }
    #undef GZ_ISSUE_B
    #undef GZ_LOAD_A
    __syncthreads();

    // stage G (32 x 384) into smem (f32)
    #pragma unroll
    for (int im = 0; im < 2; im++) {
        int r0 = im*16 + gid;
        #pragma unroll
        for (int in_ = 0; in_ < 6; in_++) {
            int cb = wid*48 + in_*8 + tig*2;
            #pragma unroll
            for (int half = 0; half < 2; half++) {
                int row = r0 + half*8;
                Gsm[row*384 + cb]     = c[im][in_][half*2 + 0];
                Gsm[row*384 + cb + 1] = c[im][in_][half*2 + 1];
            }
        }
    }
    __syncthreads();

    // GRU epilogue: 32 rows x 128 n; h stored bf16
    #pragma unroll
    for (int i = 0; i < 16; i++) {
        int idx = i*256 + tid;
        int m = idx >> 7, n = idx & 127;
        int b = brow + m;
        int ng = nb*128 + n;
        float ir  = Gsm[m*384 + n]       + bih[ng];
        float iz  = Gsm[m*384 + 128 + n] + bih[1024 + ng];
        float inn = Gsm[m*384 + 256 + n] + bih[2048 + ng];
        const float* Sb = S + (long)b*SN;
        float hr = Sb[1024 + ng], hz = Sb[2048 + ng], hn = Sb[3072 + ng];
        float r  = 1.0f / (1.0f + expf(-(ir + hr)));
        float u  = 1.0f / (1.0f + expf(-(iz + hz)));
        float nn = tanhf(inn + r * hn);
        float hp = __bfloat162float(g_h[b*DETD + ng]);
        float hnew = (1.0f - u) * nn + u * hp;
        bf16 hb = __float2bfloat16_rn(hnew);
        feat_t[(long)b*FEATD + ng] = hb;
        g_h[b*DETD + ng] = dn[b] ? (bf16)__float2bfloat16_rn(0.0f) : hb;
    }
}

// --- the fused kernel: 128 CTAs, smem = SMEMGZ ---
__global__ void __launch_bounds__(256) phaseB_k(
    float* __restrict__ S_t,
    const float* __restrict__ pe,
    const float* __restrict__ epst,
    const float* __restrict__ act,
    const bf16*  __restrict__ wihP,
    const float* __restrict__ bih,
    const unsigned char* __restrict__ dn,
    bf16* __restrict__ feat_t,
    int t)
{
    extern __shared__ uint32_t smem[];
    const int bid = blockIdx.x;

    // Phase 1: S tile (all 128 CTAs; bx 0..31, by 0..3)
    dev_sgemm64(smem, bid & 31, bid >> 5, g_h, g_WhT, S_t, g_bh);

    // grid barrier (monotonic counter; target = 128*(t+1))
    __syncthreads();
    __threadfence();
    if (threadIdx.x == 0) {
        atomicAdd(&g_bar, 1u);
        unsigned target = 128u * (unsigned)(t + 1);
        while (*(volatile unsigned*)&g_bar < target) { __nanosleep(32); }
        __threadfence();
    }
    __syncthreads();

    // Phase 2: gzgru tiles (CTAs 0..63)
    if (bid < 64) {
        dev_gz(smem, bid & 7, (bid >> 3) * 32,
               S_t, pe, epst, act, wihP, bih, dn, feat_t);
    }
}

// ---------------- weight prep (all to bf16) ----------------
__global__ void cvt_bf_k(bf16* __restrict__ dst, const float* __restrict__ src, long n)
{
    long idx = (long)blockIdx.x * blockDim.x + threadIdx.x;
    if (idx < n) dst[idx] = __float2bfloat16_rn(src[idx]);
}

__global__ void transpose_bf_k(bf16* __restrict__ dst, const float* __restrict__ src, int K, int N)
{
    long idx = (long)blockIdx.x * blockDim.x + threadIdx.x;
    if (idx >= (long)K * N) return;
    int n = (int)(idx / K), k = (int)(idx % K);
    dst[idx] = __float2bfloat16_rn(src[(long)k * N + n]);
}

__global__ void prep_whT_k(const float* __restrict__ prior_w, const float* __restrict__ prior_b,
                           const float* __restrict__ post_w,
                           const float* __restrict__ gru_whh, const float* __restrict__ gru_bhh)
{
    long idx = (long)blockIdx.x * blockDim.x + threadIdx.x;
    if (idx < (long)SN * DETD) {
        int n = (int)(idx >> 10), k = (int)(idx & 1023);
        float v;
        if (n < 512)       v = prior_w[k*512 + n];
        else if (n < 1024) v = post_w[k*512 + (n - 512)];
        else               v = gru_whh[(long)(n - 1024)*DETD + k];
        g_WhT[idx] = __float2bfloat16_rn(v);
    }
    if (idx < SN) {
        int n = (int)idx;
        g_bh[n] = (n < 512) ? prior_b[n] : (n < 1024 ? 0.0f : gru_bhh[n - 1024]);
    }
}

__global__ void prep_w1fT_k(const float* __restrict__ dec_w1, const float* __restrict__ dec_b1,
                            const float* __restrict__ rew_w1, const float* __restrict__ rew_b1)
{
    long idx = (long)blockIdx.x * blockDim.x + threadIdx.x;
    if (idx < (long)2048 * FEATD) {
        int n = (int)(idx / FEATD), k = (int)(idx % FEATD);
        float v = (n < 1024) ? dec_w1[(long)k*1024 + n] : rew_w1[(long)k*1024 + (n - 1024)];
        g_W1fT[idx] = __float2bfloat16_rn(v);
    }
    if (idx < 2048) {
        int n = (int)idx;
        g_b1f[n] = (n < 1024) ? dec_b1[n] : rew_b1[n - 1024];
    }
}

__global__ void prep_postEmbT_k(const float* __restrict__ post_w)
{
    long idx = (long)blockIdx.x * blockDim.x + threadIdx.x;
    if (idx >= (long)512*EMBD) return;
    int n = (int)(idx >> 10), k = (int)(idx & 1023);
    g_postEmbT[idx] = __float2bfloat16_rn(post_w[(long)(1024 + k)*512 + n]);
}

__global__ void prep_wihP_k(const float* __restrict__ gru_wih)
{
    long idx = (long)blockIdx.x * blockDim.x + threadIdx.x;
    if (idx >= (long)3*DETD*KIH) return;
    int n = (int)(idx / KIH), k = (int)(idx % KIH);
    g_wihP[idx] = (k < STOD+ACTD) ? __float2bfloat16_rn(gru_wih[(long)n*(STOD+ACTD) + k])
                                  : __float2bfloat16_rn(0.0f);
}

// ---------------- batched loss kernels ----------------
__global__ void klbatch_k()
{
    int row = blockIdx.x, j = threadIdx.x;
    const float* Sr = g_S_all + (size_t)row*SN;
    const float* pe = g_post_emb + (long)row*512;
    float pm = Sr[j], pl = Sr[STOD + j];
    float qm = Sr[512 + j] + pe[j];
    float ql = Sr[768 + j] + pe[256 + j];
    float vq = expf(2.0f*ql), vp = expf(2.0f*pl);
    float d  = qm - pm;
    float kl = pl - ql + (vq + d*d) / (vp + 1e-8f) - 1.0f;

    __shared__ float red[STOD];
    red[j] = kl; __syncthreads();
    for (int s = STOD/2; s > 0; s >>= 1) {
        if (j < s) red[j] += red[j + s];
        __syncthreads();
    }
    if (j == 0) g_kl[row] = 0.5f * red[0];
}

__global__ void recon_k(const float* __restrict__ obs)
{
    int r = blockIdx.x, t = threadIdx.x;
    const float* p = g_pred + (long)r*OBSD;
    const float* o = obs + ((long)r + BB)*OBSD;
    float s = 0.0f;
    for (int i = t; i < OBSD; i += 128) { float d = p[i] - o[i]; s += d*d; }
    __shared__ float red[128];
    red[t] = s; __syncthreads();
    for (int st = 64; st > 0; st >>= 1) {
        if (t < st) red[t] += red[t + st];
        __syncthreads();
    }
    if (t == 0) g_recon[r] = red[0] / (float)OBSD;
}

__global__ void rew_k(const float* __restrict__ rewards,
                      const float* __restrict__ rew_w2, const float* __restrict__ rew_b2)
{
    int r = blockIdx.x, t = threadIdx.x;
    const bf16* hrow = g_H1 + (long)r*2048 + 1024;
    float s = 0.0f;
    for (int i = t; i < 1024; i += 256) s += __bfloat162float(hrow[i]) * rew_w2[i];
    __shared__ float red[256];
    red[t] = s; __syncthreads();
    for (int st = 128; st > 0; st >>= 1) {
        if (t < st) red[t] += red[t + st];
        __syncthreads();
    }
    if (t == 0) {
        float pred = red[0] + rew_b2[0];
        float d = pred - rewards[r];
        g_rewl[r] = d*d;
    }
}

__global__ void final_k(float* __restrict__ out)
{
    int t = threadIdx.x;
    float a = 0, b = 0, c = 0;
    for (int i = t; i < RR; i += 256) { a += g_recon[i]; b += g_rewl[i]; c += g_kl[i]; }
    __shared__ float sa[256], sb[256], sc[256];
    sa[t] = a; sb[t] = b; sc[t] = c; __syncthreads();
    for (int s = 128; s > 0; s >>= 1) {
        if (t < s) { sa[t] += sa[t+s]; sb[t] += sb[t+s]; sc[t] += sc[t+s]; }
        __syncthreads();
    }
    if (t == 0) {
        float recon = sa[0] / (float)RR;
        float rew   = sb[0] / (float)RR;
        float kl    = sc[0] / (float)RR;
        out[0] = recon + rew + kl;
        out[1] = recon;
        out[2] = rew;
        out[3] = kl;
    }
}

// ---------------- host ----------------
#define SMEM128 ((2*128*32 + 2*128*32)*4)   // 65536
#define SMEMGZ  ((1024 + 2*12288)*4)        // 102400

static inline void run128(const bf16* A, int lda, const bf16* B, int ldb,
                          void* C, int ldc, const float* bias,
                          int M, int N, int K, int relu, int outbf)
{
    dim3 grid(N/128, M/128);
    ca_gemm<128><<<grid, 256, SMEM128>>>(A, lda, B, ldb, C, ldc, bias, K, relu, outbf);
}

extern "C" void kernel_launch(void* const* d_in, const int* in_sizes, int n_in,
                              void* d_out, int out_size)
{
    const float* obs     = (const float*)d_in[0];
    const float* actions = (const float*)d_in[1];
    const float* rewards = (const float*)d_in[2];
    const unsigned char* dones = (const unsigned char*)d_in[3];
    const float* eps     = (const float*)d_in[4];
    const float* enc_w1  = (const float*)d_in[5];
    const float* enc_b1  = (const float*)d_in[6];
    const float* enc_w2  = (const float*)d_in[7];
    const float* enc_b2  = (const float*)d_in[8];
    const float* gru_wih = (const float*)d_in[9];
    const float* gru_whh = (const float*)d_in[10];
    const float* gru_bih = (const float*)d_in[11];
    const float* gru_bhh = (const float*)d_in[12];
    const float* prior_w = (const float*)d_in[13];
    const float* prior_b = (const float*)d_in[14];
    const float* post_w  = (const float*)d_in[15];
    const float* post_b  = (const float*)d_in[16];
    const float* dec_w1  = (const float*)d_in[17];
    const float* dec_b1  = (const float*)d_in[18];
    const float* dec_w2  = (const float*)d_in[19];
    const float* dec_b2  = (const float*)d_in[20];
    const float* rew_w1  = (const float*)d_in[21];
    const float* rew_b1  = (const float*)d_in[22];
    const float* rew_w2  = (const float*)d_in[23];
    const float* rew_b2  = (const float*)d_in[24];
    float* out = (float*)d_out;

    cudaFuncSetAttribute(ca_gemm<128>, cudaFuncAttributeMaxDynamicSharedMemorySize, SMEM128);
    cudaFuncSetAttribute(phaseB_k,     cudaFuncAttributeMaxDynamicSharedMemorySize, SMEMGZ);

    bf16 *p_obsb, *p_embh, *p_emb, *p_feat, *p_H1, *p_h;
    bf16 *p_WhT, *p_wihP, *p_encw1T, *p_encw2T, *p_postEmbT, *p_decw2T, *p_W1fT;
    float *p_post_emb, *p_pred, *p_S_all, *p_bh, *p_b1f;
    cudaGetSymbolAddress((void**)&p_obsb, g_obsb);
    cudaGetSymbolAddress((void**)&p_embh, g_embh);
    cudaGetSymbolAddress((void**)&p_emb, g_emb);
    cudaGetSymbolAddress((void**)&p_feat, g_feat);
    cudaGetSymbolAddress((void**)&p_H1, g_H1);
    cudaGetSymbolAddress((void**)&p_h, g_h);
    cudaGetSymbolAddress((void**)&p_WhT, g_WhT);
    cudaGetSymbolAddress((void**)&p_wihP, g_wihP);
    cudaGetSymbolAddress((void**)&p_encw1T, g_encw1T);
    cudaGetSymbolAddress((void**)&p_encw2T, g_encw2T);
    cudaGetSymbolAddress((void**)&p_postEmbT, g_postEmbT);
    cudaGetSymbolAddress((void**)&p_decw2T, g_decw2T);
    cudaGetSymbolAddress((void**)&p_W1fT, g_W1fT);
    cudaGetSymbolAddress((void**)&p_post_emb, g_post_emb);
    cudaGetSymbolAddress((void**)&p_pred, g_pred);
    cudaGetSymbolAddress((void**)&p_S_all, g_S_all);
    cudaGetSymbolAddress((void**)&p_bh, g_bh);
    cudaGetSymbolAddress((void**)&p_b1f, g_b1f);
    void* p_bar; cudaGetSymbolAddress(&p_bar, g_bar);

    cudaMemsetAsync(p_h, 0, (size_t)BB*DETD*sizeof(bf16));
    cudaMemsetAsync(p_bar, 0, sizeof(unsigned));

    // ---- weight + input prep ----
    {
        long n;
        n = (long)RR*OBSD;
        cvt_bf_k<<<(unsigned)((n+255)/256), 256>>>(p_obsb, obs, n);
        n = (long)3*DETD*KIH;
        prep_wihP_k<<<(unsigned)((n+255)/256), 256>>>(gru_wih);
        n = (long)EMBD*OBSD;
        transpose_bf_k<<<(unsigned)((n+255)/256), 256>>>(p_encw1T, enc_w1, OBSD, EMBD);
        n = (long)EMBD*EMBD;
        transpose_bf_k<<<(unsigned)((n+255)/256), 256>>>(p_encw2T, enc_w2, EMBD, EMBD);
        n = (long)OBSD*EMBD;
        transpose_bf_k<<<(unsigned)((n+255)/256), 256>>>(p_decw2T, dec_w2, EMBD, OBSD);
        n = (long)512*EMBD;
        prep_postEmbT_k<<<(unsigned)((n+255)/256), 256>>>(post_w);
        n = (long)SN*DETD;
        prep_whT_k<<<(unsigned)((n+255)/256), 256>>>(prior_w, prior_b, post_w, gru_whh, gru_bhh);
        n = (long)2048*FEATD;
        prep_w1fT_k<<<(unsigned)((n+255)/256), 256>>>(dec_w1, dec_b1, rew_w1, rew_b1);
    }

    // ---- Phase A: time-batched precompute ----
    run128(p_obsb, OBSD, p_encw1T, OBSD, p_embh, EMBD, enc_b1, RR, EMBD, OBSD, 1, 1);
    run128(p_embh, EMBD, p_encw2T, EMBD, p_emb, EMBD, enc_b2, RR, EMBD, EMBD, 1, 1);
    run128(p_emb, EMBD, p_postEmbT, EMBD, p_post_emb, 512, post_b, RR, 512, EMBD, 0, 0);

    // ---- Phase B: sequential recurrence (1 fused launch per step) ----
    for (int t = 0; t < TS; t++) {
        phaseB_k<<<128, 256, SMEMGZ>>>(
            p_S_all + (size_t)t*BB*SN,
            p_post_emb + (size_t)t*BB*512,
            eps + (size_t)t*BB*STOD,
            actions + (size_t)t*BB*ACTD,
            p_wihP, gru_bih,
            dones + (size_t)t*BB,
            p_feat + (size_t)t*BB*FEATD,
            t);
    }

    // ---- Phase C: batched KL + decoder / reward / losses ----
    klbatch_k<<<RR, STOD>>>();
    run128(p_feat, FEATD, p_W1fT, FEATD, p_H1, 2048, p_b1f, RR, 2048, FEATD, 1, 1);
    run128(p_H1, 2048, p_decw2T, EMBD, p_pred, OBSD, dec_b2, RR, OBSD, EMBD, 0, 0);
    recon_k<<<RR, 128>>>(obs);
    rew_k<<<RR, 256>>>(rewards, rew_w2, rew_b2);
    final_k<<<1, 256>>>(out);

    (void)in_sizes; (void)n_in; (void)out_size;
}

// round 17
// speedup vs baseline: 1.1468x; 1.1468x over previous
#include <cuda_runtime.h>
#include <cuda_bf16.h>
#include <math.h>
#include <stdint.h>

typedef __nv_bfloat16 bf16;

// ---------------- problem constants ----------------
#define TS   63
#define BB   256
#define OBSD 512
#define ACTD 32
#define EMBD 1024
#define DETD 1024
#define STOD 256
#define RR   (TS*BB)
#define FEATD (DETD+STOD)   // 1280
#define SN   4096           // S width: [prior 512 | post 512 | gh 3072]
#define KIH  320            // padded gzgru K: [z 256 | a 32 | pad 32]
#define SC   16             // time-steps per Phase-A chunk
#define NCH  4              // number of chunks (16+16+16+15)

// ---------------- device scratch ----------------
__device__ bf16  g_obsb[RR*OBSD];
__device__ bf16  g_embh[RR*EMBD];
__device__ bf16  g_emb [RR*EMBD];
__device__ float g_post_emb[RR*512];
__device__ bf16  g_feat[RR*FEATD];          // [h | z]
__device__ bf16  g_H1  [RR*2048];
__device__ float g_pred[RR*OBSD];
__device__ float g_S_all[(size_t)RR*SN];
__device__ bf16  g_h[BB*DETD];
__device__ float g_kl[RR];
__device__ float g_recon[RR];
__device__ float g_rewl[RR];
// weights (bf16), pre-transposed to [N,K]
__device__ bf16  g_WhT[SN*DETD];            // [prior | post_h | whh^T]
__device__ float g_bh[SN];
__device__ bf16  g_wihP[3*DETD*KIH];        // padded [3072, 320]
__device__ bf16  g_encw1T[EMBD*OBSD];
__device__ bf16  g_encw2T[EMBD*EMBD];
__device__ bf16  g_postEmbT[512*EMBD];
__device__ bf16  g_decw2T[OBSD*EMBD];
__device__ bf16  g_W1fT[2048*FEATD];
__device__ float g_b1f[2048];

__device__ __forceinline__ uint32_t pack_bf2(float a, float b) {
    __nv_bfloat162 h = __floats2bfloat162_rn(a, b);
    return *(uint32_t*)&h;
}
__device__ __forceinline__ int swz(int r, int k) {   // k = uint32 col 0..31
    return r*32 + (k ^ ((r & 7) << 2));
}
__device__ __forceinline__ void cp16(uint32_t saddr, const void* g) {
    asm volatile("cp.async.cg.shared.global [%0], [%1], 16;" :: "r"(saddr), "l"(g));
}
__device__ __forceinline__ void cp_commit() {
    asm volatile("cp.async.commit_group;" ::: "memory");
}
template<int N> __device__ __forceinline__ void cp_wait() {
    asm volatile("cp.async.wait_group %0;" :: "n"(N) : "memory");
}
#define MMA_BF16(c, a, b) \
    asm volatile( \
        "mma.sync.aligned.m16n8k16.row.col.f32.bf16.bf16.f32 " \
        "{%0,%1,%2,%3}, {%4,%5,%6,%7}, {%8,%9}, {%0,%1,%2,%3};" \
        : "+f"((c)[0]), "+f"((c)[1]), "+f"((c)[2]), "+f"((c)[3]) \
        : "r"((a)[0]), "r"((a)[1]), "r"((a)[2]), "r"((a)[3]), \
          "r"((b)[0]), "r"((b)[1]))

// ================= cp.async double-buffered bf16 GEMM =================
// C[M,N] = act(A[M,K] @ B[N,K]^T + bias); tile BM x 128; K-chunk 64 bf16.
template<int BM>
__global__ void __launch_bounds__(256) ca_gemm(
    const bf16* __restrict__ A, int lda,
    const bf16* __restrict__ B, int ldb,
    void* __restrict__ Cv, int ldc,
    const float* __restrict__ bias, int K, int relu, int outbf)
{
    extern __shared__ uint32_t smem[];
    uint32_t* As = smem;               // 2 * BM*32
    uint32_t* Bs = smem + 2*BM*32;     // 2 * 128*32

    const int tid = threadIdx.x;
    const int wid = tid >> 5, lane = tid & 31;
    constexpr int WM   = BM/32;
    constexpr int WN   = 8/WM;
    constexpr int NCOL = 128/WN;
    constexpr int NAT  = NCOL/8;
    const int warp_m = wid % WM;
    const int warp_n = wid / WM;
    const int gid = lane >> 2, tig = lane & 3;
    const long brow = (long)blockIdx.y * BM;
    const long bcol = (long)blockIdx.x * 128;
    const int nch = K >> 6;

    const uint32_t as_u = (uint32_t)__cvta_generic_to_shared(As);
    const uint32_t bs_u = (uint32_t)__cvta_generic_to_shared(Bs);

    float c[2][NAT][4];
    #pragma unroll
    for (int im = 0; im < 2; im++)
        #pragma unroll
        for (int in_ = 0; in_ < NAT; in_++)
            #pragma unroll
            for (int j = 0; j < 4; j++) c[im][in_][j] = 0.0f;

    constexpr int NA = BM/32;
    int fr[NA], fkc[NA];
    #pragma unroll
    for (int i = 0; i < NA; i++) {
        int lin = i*256 + tid;
        fr[i]  = lin >> 3;
        fkc[i] = (lin & 7) << 2;
    }
    int gr[4], gkc[4];
    #pragma unroll
    for (int i = 0; i < 4; i++) {
        int lin = i*256 + tid;
        gr[i]  = lin >> 3;
        gkc[i] = (lin & 7) << 2;
    }

    #define CA_ISSUE(cc)                                                           \
    do {                                                                           \
        int k0 = (cc) << 6; int buf = (cc) & 1;                                    \
        _Pragma("unroll")                                                          \
        for (int i = 0; i < NA; i++)                                               \
            cp16(as_u + (uint32_t)(buf*BM*32 + swz(fr[i], fkc[i]))*4,              \
                 A + (brow + fr[i])*(long)lda + k0 + fkc[i]*2);                    \
        _Pragma("unroll")                                                          \
        for (int i = 0; i < 4; i++)                                                \
            cp16(bs_u + (uint32_t)(buf*128*32 + swz(gr[i], gkc[i]))*4,             \
                 B + (bcol + gr[i])*(long)ldb + k0 + gkc[i]*2);                    \
        cp_commit();                                                               \
    } while (0)

    CA_ISSUE(0);

    for (int cch = 0; cch < nch; cch++) {
        if (cch + 1 < nch) { CA_ISSUE(cch + 1); cp_wait<1>(); }
        else               { cp_wait<0>(); }
        __syncthreads();

        const uint32_t* Ap = As + (cch & 1)*BM*32;
        const uint32_t* Bp = Bs + (cch & 1)*128*32;

        #pragma unroll
        for (int kb = 0; kb < 4; kb++) {
            const int kk = kb*8 + tig;
            uint32_t af[2][4];
            #pragma unroll
            for (int ia = 0; ia < 2; ia++) {
                int m0 = warp_m*32 + ia*16 + gid;
                int x  = (m0 & 7) << 2;
                af[ia][0] = Ap[m0*32     + (kk     ^ x)];
                af[ia][1] = Ap[(m0+8)*32 + (kk     ^ x)];
                af[ia][2] = Ap[m0*32     + ((kk+4) ^ x)];
                af[ia][3] = Ap[(m0+8)*32 + ((kk+4) ^ x)];
            }
            uint32_t bf[NAT][2];
            #pragma unroll
            for (int nb = 0; nb < NAT; nb++) {
                int n = warp_n*NCOL + nb*8 + gid;
                int x = (n & 7) << 2;
                bf[nb][0] = Bp[n*32 + (kk     ^ x)];
                bf[nb][1] = Bp[n*32 + ((kk+4) ^ x)];
            }
            #pragma unroll
            for (int im = 0; im < 2; im++)
                #pragma unroll
                for (int in_ = 0; in_ < NAT; in_++)
                    MMA_BF16(c[im][in_], af[im], bf[in_]);
        }
        __syncthreads();
    }
    #undef CA_ISSUE

    #pragma unroll
    for (int im = 0; im < 2; im++) {
        long r0 = brow + warp_m*32 + im*16 + gid;
        #pragma unroll
        for (int in_ = 0; in_ < NAT; in_++) {
            long cb = bcol + warp_n*NCOL + in_*8 + tig*2;
            #pragma unroll
            for (int half = 0; half < 2; half++) {
                long row = r0 + half*8;
                float v0 = c[im][in_][half*2 + 0];
                float v1 = c[im][in_][half*2 + 1];
                if (bias) { v0 += bias[cb]; v1 += bias[cb + 1]; }
                if (relu) { v0 = fmaxf(v0, 0.f); v1 = fmaxf(v1, 0.f); }
                if (outbf) {
                    *(uint32_t*)((bf16*)Cv + row*(long)ldc + cb) = pack_bf2(v0, v1);
                } else {
                    *(float2*)((float*)Cv + row*(long)ldc + cb) = make_float2(v0, v1);
                }
            }
        }
    }
}

// ================= fused Gz + GRU kernel (bf16) =================
// grid (nb=8, tm=8). Tile: 32 rows x 384 cols (3 gates x 128 n). K=320 (5 chunks).
__global__ void __launch_bounds__(256) gzgru_k(
    const float* __restrict__ S,          // [BB, 4096] f32
    const float* __restrict__ pe,         // [BB, 512]  f32
    const float* __restrict__ epst,       // [BB, 256]  f32
    const float* __restrict__ act,        // [BB, 32]   f32
    const bf16*  __restrict__ wihP,       // [3072, 320] bf16
    const float* __restrict__ bih,        // [3072]
    const unsigned char* __restrict__ dn, // [BB]
    bf16* __restrict__ feat_t)            // [BB, FEATD] bf16
{
    extern __shared__ uint32_t smem[];
    uint32_t* As = smem;                  // 32*32 = 1024 u32
    uint32_t* Bs = smem + 1024;           // 2 * 384*32 = 24576 u32
    float* Gsm = (float*)smem;            // alias, used post-GEMM

    const int tid = threadIdx.x;
    const int wid = tid >> 5, lane = tid & 31;
    const int gid = lane >> 2, tig = lane & 3;
    const int nb = blockIdx.x;
    const int brow = blockIdx.y * 32;
    const int nch = 5;                    // K = 320

    const uint32_t bs_u = (uint32_t)__cvta_generic_to_shared(Bs);

    float c[2][6][4];
    #pragma unroll
    for (int im = 0; im < 2; im++)
        #pragma unroll
        for (int in_ = 0; in_ < 6; in_++)
            #pragma unroll
            for (int j = 0; j < 4; j++) c[im][in_][j] = 0.0f;

    const int fr = tid >> 3, fkc = (tid & 7) << 2;
    int gr[12], gkc[12];
    #pragma unroll
    for (int i = 0; i < 12; i++) {
        int lin = i*256 + tid;
        gr[i]  = lin >> 3;
        gkc[i] = (lin & 7) << 2;
    }

    #define GZ_ISSUE_B(cc)                                                         \
    do {                                                                           \
        int k0 = (cc) << 6; int buf = (cc) & 1;                                    \
        _Pragma("unroll")                                                          \
        for (int i = 0; i < 12; i++) {                                             \
            int grow = (gr[i] >> 7)*1024 + nb*128 + (gr[i] & 127);                 \
            cp16(bs_u + (uint32_t)(buf*12288 + swz(gr[i], gkc[i]))*4,              \
                 wihP + (long)grow*KIH + k0 + gkc[i]*2);                           \
        }                                                                          \
        cp_commit();                                                               \
    } while (0)

    uint4 sA;
    #define GZ_LOAD_A(cc)                                                          \
    do {                                                                           \
        int j = ((cc) << 6) + (fkc << 1);                                          \
        int b = brow + fr;                                                         \
        if (j < 256) {                                                             \
            uint32_t pk[4];                                                        \
            _Pragma("unroll")                                                      \
            for (int q = 0; q < 2; q++) {                                          \
                int jj = j + q*4;                                                  \
                float4 qm = *(const float4*)(S + (long)b*SN + 512 + jj);           \
                float4 p1 = *(const float4*)(pe + (long)b*512 + jj);               \
                float4 ql = *(const float4*)(S + (long)b*SN + 768 + jj);           \
                float4 p2 = *(const float4*)(pe + (long)b*512 + 256 + jj);         \
                float4 e  = *(const float4*)(epst + (long)b*256 + jj);             \
                float z0 = (qm.x + p1.x) + e.x * expf(ql.x + p2.x);                \
                float z1 = (qm.y + p1.y) + e.y * expf(ql.y + p2.y);                \
                float z2 = (qm.z + p1.z) + e.z * expf(ql.z + p2.z);                \
                float z3 = (qm.w + p1.w) + e.w * expf(ql.w + p2.w);                \
                pk[q*2]   = pack_bf2(z0, z1);                                      \
                pk[q*2+1] = pack_bf2(z2, z3);                                      \
            }                                                                      \
            sA = make_uint4(pk[0], pk[1], pk[2], pk[3]);                           \
            if (nb == 0) *(uint4*)(feat_t + (long)b*FEATD + DETD + j) = sA;        \
        } else if (j < 288) {                                                      \
            float4 a0 = *(const float4*)(act + (long)b*ACTD + (j - 256));          \
            float4 a1 = *(const float4*)(act + (long)b*ACTD + (j - 256) + 4);      \
            sA = make_uint4(pack_bf2(a0.x, a0.y), pack_bf2(a0.z, a0.w),            \
                            pack_bf2(a1.x, a1.y), pack_bf2(a1.z, a1.w));           \
        } else {                                                                   \
            sA = make_uint4(0, 0, 0, 0);                                           \
        }                                                                          \
    } while (0)

    GZ_ISSUE_B(0);
    GZ_LOAD_A(0);

    for (int cch = 0; cch < nch; cch++) {
        __syncthreads();
        *(uint4*)&As[swz(fr, fkc)] = sA;
        if (cch + 1 < nch) { GZ_ISSUE_B(cch + 1); cp_wait<1>(); }
        else               { cp_wait<0>(); }
        __syncthreads();
        if (cch + 1 < nch) GZ_LOAD_A(cch + 1);

        const uint32_t* Ap = As;
        const uint32_t* Bp = Bs + (cch & 1)*12288;

        #pragma unroll
        for (int kb = 0; kb < 4; kb++) {
            const int kk = kb*8 + tig;
            uint32_t af[2][4];
            #pragma unroll
            for (int ia = 0; ia < 2; ia++) {
                int m0 = ia*16 + gid;
                int x  = (m0 & 7) << 2;
                af[ia][0] = Ap[m0*32     + (kk     ^ x)];
                af[ia][1] = Ap[(m0+8)*32 + (kk     ^ x)];
                af[ia][2] = Ap[m0*32     + ((kk+4) ^ x)];
                af[ia][3] = Ap[(m0+8)*32 + ((kk+4) ^ x)];
            }
            uint32_t bf[6][2];
            #pragma unroll
            for (int nbi = 0; nbi < 6; nbi++) {
                int n = wid*48 + nbi*8 + gid;
                int x = (n & 7) << 2;
                bf[nbi][0] = Bp[n*32 + (kk     ^ x)];
                bf[nbi][1] = Bp[n*32 + ((kk+4) ^ x)];
            }
            #pragma unroll
            for (int im = 0; im < 2; im++)
                #pragma unroll
                for (int in_ = 0; in_ < 6; in_++)
                    MMA_BF16(c[im][in_], af[im], bf[in_]);
        }
    }
    #undef GZ_ISSUE_B
    #undef GZ_LOAD_A
    __syncthreads();

    // stage G (32 x 384) into smem (f32)
    #pragma unroll
    for (int im = 0; im < 2; im++) {
        int r0 = im*16 + gid;
        #pragma unroll
        for (int in_ = 0; in_ < 6; in_++) {
            int cb = wid*48 + in_*8 + tig*2;
            #pragma unroll
            for (int half = 0; half < 2; half++) {
                int row = r0 + half*8;
                Gsm[row*384 + cb]     = c[im][in_][half*2 + 0];
                Gsm[row*384 + cb + 1] = c[im][in_][half*2 + 1];
            }
        }
    }
    __syncthreads();

    // GRU epilogue: 32 rows x 128 n; h stored bf16
    #pragma unroll
    for (int i = 0; i < 16; i++) {
        int idx = i*256 + tid;
        int m = idx >> 7, n = idx & 127;
        int b = brow + m;
        int ng = nb*128 + n;
        float ir  = Gsm[m*384 + n]       + bih[ng];
        float iz  = Gsm[m*384 + 128 + n] + bih[1024 + ng];
        float inn = Gsm[m*384 + 256 + n] + bih[2048 + ng];
        const float* Sb = S + (long)b*SN;
        float hr = Sb[1024 + ng], hz = Sb[2048 + ng], hn = Sb[3072 + ng];
        float r  = 1.0f / (1.0f + expf(-(ir + hr)));
        float u  = 1.0f / (1.0f + expf(-(iz + hz)));
        float nn = tanhf(inn + r * hn);
        float hp = __bfloat162float(g_h[b*DETD + ng]);
        float hnew = (1.0f - u) * nn + u * hp;
        bf16 hb = __float2bfloat16_rn(hnew);
        feat_t[(long)b*FEATD + ng] = hb;
        g_h[b*DETD + ng] = dn[b] ? (bf16)__float2bfloat16_rn(0.0f) : hb;
    }
}

// ---------------- weight prep (all to bf16) ----------------
__global__ void cvt_bf_k(bf16* __restrict__ dst, const float* __restrict__ src, long n)
{
    long idx = (long)blockIdx.x * blockDim.x + threadIdx.x;
    if (idx < n) dst[idx] = __float2bfloat16_rn(src[idx]);
}

__global__ void transpose_bf_k(bf16* __restrict__ dst, const float* __restrict__ src, int K, int N)
{
    long idx = (long)blockIdx.x * blockDim.x + threadIdx.x;
    if (idx >= (long)K * N) return;
    int n = (int)(idx / K), k = (int)(idx % K);
    dst[idx] = __float2bfloat16_rn(src[(long)k * N + n]);
}

__global__ void prep_whT_k(const float* __restrict__ prior_w, const float* __restrict__ prior_b,
                           const float* __restrict__ post_w,
                           const float* __restrict__ gru_whh, const float* __restrict__ gru_bhh)
{
    long idx = (long)blockIdx.x * blockDim.x + threadIdx.x;
    if (idx < (long)SN * DETD) {
        int n = (int)(idx >> 10), k = (int)(idx & 1023);
        float v;
        if (n < 512)       v = prior_w[k*512 + n];
        else if (n < 1024) v = post_w[k*512 + (n - 512)];
        else               v = gru_whh[(long)(n - 1024)*DETD + k];
        g_WhT[idx] = __float2bfloat16_rn(v);
    }
    if (idx < SN) {
        int n = (int)idx;
        g_bh[n] = (n < 512) ? prior_b[n] : (n < 1024 ? 0.0f : gru_bhh[n - 1024]);
    }
}

__global__ void prep_w1fT_k(const float* __restrict__ dec_w1, const float* __restrict__ dec_b1,
                            const float* __restrict__ rew_w1, const float* __restrict__ rew_b1)
{
    long idx = (long)blockIdx.x * blockDim.x + threadIdx.x;
    if (idx < (long)2048 * FEATD) {
        int n = (int)(idx / FEATD), k = (int)(idx % FEATD);
        float v = (n < 1024) ? dec_w1[(long)k*1024 + n] : rew_w1[(long)k*1024 + (n - 1024)];
        g_W1fT[idx] = __float2bfloat16_rn(v);
    }
    if (idx < 2048) {
        int n = (int)idx;
        g_b1f[n] = (n < 1024) ? dec_b1[n] : rew_b1[n - 1024];
    }
}

__global__ void prep_postEmbT_k(const float* __restrict__ post_w)
{
    long idx = (long)blockIdx.x * blockDim.x + threadIdx.x;
    if (idx >= (long)512*EMBD) return;
    int n = (int)(idx >> 10), k = (int)(idx & 1023);
    g_postEmbT[idx] = __float2bfloat16_rn(post_w[(long)(1024 + k)*512 + n]);
}

__global__ void prep_wihP_k(const float* __restrict__ gru_wih)
{
    long idx = (long)blockIdx.x * blockDim.x + threadIdx.x;
    if (idx >= (long)3*DETD*KIH) return;
    int n = (int)(idx / KIH), k = (int)(idx % KIH);
    g_wihP[idx] = (k < STOD+ACTD) ? __float2bfloat16_rn(gru_wih[(long)n*(STOD+ACTD) + k])
                                  : __float2bfloat16_rn(0.0f);
}

// ---------------- batched loss kernels ----------------
__global__ void klbatch_k()
{
    int row = blockIdx.x, j = threadIdx.x;
    const float* Sr = g_S_all + (size_t)row*SN;
    const float* pe = g_post_emb + (long)row*512;
    float pm = Sr[j], pl = Sr[STOD + j];
    float qm = Sr[512 + j] + pe[j];
    float ql = Sr[768 + j] + pe[256 + j];
    float vq = expf(2.0f*ql), vp = expf(2.0f*pl);
    float d  = qm - pm;
    float kl = pl - ql + (vq + d*d) / (vp + 1e-8f) - 1.0f;

    __shared__ float red[STOD];
    red[j] = kl; __syncthreads();
    for (int s = STOD/2; s > 0; s >>= 1) {
        if (j < s) red[j] += red[j + s];
        __syncthreads();
    }
    if (j == 0) g_kl[row] = 0.5f * red[0];
}

__global__ void recon_k(const float* __restrict__ obs)
{
    int r = blockIdx.x, t = threadIdx.x;
    const float* p = g_pred + (long)r*OBSD;
    const float* o = obs + ((long)r + BB)*OBSD;
    float s = 0.0f;
    for (int i = t; i < OBSD; i += 128) { float d = p[i] - o[i]; s += d*d; }
    __shared__ float red[128];
    red[t] = s; __syncthreads();
    for (int st = 64; st > 0; st >>= 1) {
        if (t < st) red[t] += red[t + st];
        __syncthreads();
    }
    if (t == 0) g_recon[r] = red[0] / (float)OBSD;
}

__global__ void rew_k(const float* __restrict__ rewards,
                      const float* __restrict__ rew_w2, const float* __restrict__ rew_b2)
{
    int r = blockIdx.x, t = threadIdx.x;
    const bf16* hrow = g_H1 + (long)r*2048 + 1024;
    float s = 0.0f;
    for (int i = t; i < 1024; i += 256) s += __bfloat162float(hrow[i]) * rew_w2[i];
    __shared__ float red[256];
    red[t] = s; __syncthreads();
    for (int st = 128; st > 0; st >>= 1) {
        if (t < st) red[t] += red[t + st];
        __syncthreads();
    }
    if (t == 0) {
        float pred = red[0] + rew_b2[0];
        float d = pred - rewards[r];
        g_rewl[r] = d*d;
    }
}

__global__ void final_k(float* __restrict__ out)
{
    int t = threadIdx.x;
    float a = 0, b = 0, c = 0;
    for (int i = t; i < RR; i += 256) { a += g_recon[i]; b += g_rewl[i]; c += g_kl[i]; }
    __shared__ float sa[256], sb[256], sc[256];
    sa[t] = a; sb[t] = b; sc[t] = c; __syncthreads();
    for (int s = 128; s > 0; s >>= 1) {
        if (t < s) { sa[t] += sa[t+s]; sb[t] += sb[t+s]; sc[t] += sc[t+s]; }
        __syncthreads();
    }
    if (t == 0) {
        float recon = sa[0] / (float)RR;
        float rew   = sb[0] / (float)RR;
        float kl    = sc[0] / (float)RR;
        out[0] = recon + rew + kl;
        out[1] = recon;
        out[2] = rew;
        out[3] = kl;
    }
}

// ---------------- host ----------------
#define SMEM128 ((2*128*32 + 2*128*32)*4)   // 65536
#define SMEM64  ((2*64*32  + 2*128*32)*4)   // 49152
#define SMEMGZ  ((1024 + 2*12288)*4)        // 102400

static inline void run128_s(cudaStream_t st, const bf16* A, int lda, const bf16* B, int ldb,
                            void* C, int ldc, const float* bias,
                            int M, int N, int K, int relu, int outbf)
{
    dim3 grid(N/128, M/128);
    ca_gemm<128><<<grid, 256, SMEM128, st>>>(A, lda, B, ldb, C, ldc, bias, K, relu, outbf);
}
static inline void run64_s(cudaStream_t st, const bf16* A, int lda, const bf16* B, int ldb,
                           void* C, int ldc, const float* bias,
                           int M, int N, int K, int relu, int outbf)
{
    dim3 grid(N/128, M/64);
    ca_gemm<64><<<grid, 256, SMEM64, st>>>(A, lda, B, ldb, C, ldc, bias, K, relu, outbf);
}

extern "C" void kernel_launch(void* const* d_in, const int* in_sizes, int n_in,
                              void* d_out, int out_size)
{
    const float* obs     = (const float*)d_in[0];
    const float* actions = (const float*)d_in[1];
    const float* rewards = (const float*)d_in[2];
    const unsigned char* dones = (const unsigned char*)d_in[3];
    const float* eps     = (const float*)d_in[4];
    const float* enc_w1  = (const float*)d_in[5];
    const float* enc_b1  = (const float*)d_in[6];
    const float* enc_w2  = (const float*)d_in[7];
    const float* enc_b2  = (const float*)d_in[8];
    const float* gru_wih = (const float*)d_in[9];
    const float* gru_whh = (const float*)d_in[10];
    const float* gru_bih = (const float*)d_in[11];
    const float* gru_bhh = (const float*)d_in[12];
    const float* prior_w = (const float*)d_in[13];
    const float* prior_b = (const float*)d_in[14];
    const float* post_w  = (const float*)d_in[15];
    const float* post_b  = (const float*)d_in[16];
    const float* dec_w1  = (const float*)d_in[17];
    const float* dec_b1  = (const float*)d_in[18];
    const float* dec_w2  = (const float*)d_in[19];
    const float* dec_b2  = (const float*)d_in[20];
    const float* rew_w1  = (const float*)d_in[21];
    const float* rew_b1  = (const float*)d_in[22];
    const float* rew_w2  = (const float*)d_in[23];
    const float* rew_b2  = (const float*)d_in[24];
    float* out = (float*)d_out;

    cudaFuncSetAttribute(ca_gemm<128>, cudaFuncAttributeMaxDynamicSharedMemorySize, SMEM128);
    cudaFuncSetAttribute(ca_gemm<64>,  cudaFuncAttributeMaxDynamicSharedMemorySize, SMEM64);
    cudaFuncSetAttribute(gzgru_k,      cudaFuncAttributeMaxDynamicSharedMemorySize, SMEMGZ);

    // side stream + events (created once; reused across calls and under capture)
    static cudaStream_t s2 = nullptr;
    static cudaEvent_t evFork, evPE[NCH], evSide;
    if (!s2) {
        cudaStreamCreateWithFlags(&s2, cudaStreamNonBlocking);
        cudaEventCreateWithFlags(&evFork, cudaEventDisableTiming);
        for (int i = 0; i < NCH; i++) cudaEventCreateWithFlags(&evPE[i], cudaEventDisableTiming);
        cudaEventCreateWithFlags(&evSide, cudaEventDisableTiming);
    }

    bf16 *p_obsb, *p_embh, *p_emb, *p_feat, *p_H1, *p_h;
    bf16 *p_WhT, *p_wihP, *p_encw1T, *p_encw2T, *p_postEmbT, *p_decw2T, *p_W1fT;
    float *p_post_emb, *p_pred, *p_S_all, *p_bh, *p_b1f;
    cudaGetSymbolAddress((void**)&p_obsb, g_obsb);
    cudaGetSymbolAddress((void**)&p_embh, g_embh);
    cudaGetSymbolAddress((void**)&p_emb, g_emb);
    cudaGetSymbolAddress((void**)&p_feat, g_feat);
    cudaGetSymbolAddress((void**)&p_H1, g_H1);
    cudaGetSymbolAddress((void**)&p_h, g_h);
    cudaGetSymbolAddress((void**)&p_WhT, g_WhT);
    cudaGetSymbolAddress((void**)&p_wihP, g_wihP);
    cudaGetSymbolAddress((void**)&p_encw1T, g_encw1T);
    cudaGetSymbolAddress((void**)&p_encw2T, g_encw2T);
    cudaGetSymbolAddress((void**)&p_postEmbT, g_postEmbT);
    cudaGetSymbolAddress((void**)&p_decw2T, g_decw2T);
    cudaGetSymbolAddress((void**)&p_W1fT, g_W1fT);
    cudaGetSymbolAddress((void**)&p_post_emb, g_post_emb);
    cudaGetSymbolAddress((void**)&p_pred, g_pred);
    cudaGetSymbolAddress((void**)&p_S_all, g_S_all);
    cudaGetSymbolAddress((void**)&p_bh, g_bh);
    cudaGetSymbolAddress((void**)&p_b1f, g_b1f);

    // ---- fork side stream ----
    cudaEventRecord(evFork, 0);
    cudaStreamWaitEvent(s2, evFork, 0);

    // ---- side stream: encoder chain (chunked) + Phase-C weight prep ----
    {
        long n;
        n = (long)RR*OBSD;
        cvt_bf_k<<<(unsigned)((n+255)/256), 256, 0, s2>>>(p_obsb, obs, n);
        n = (long)EMBD*OBSD;
        transpose_bf_k<<<(unsigned)((n+255)/256), 256, 0, s2>>>(p_encw1T, enc_w1, OBSD, EMBD);
        n = (long)EMBD*EMBD;
        transpose_bf_k<<<(unsigned)((n+255)/256), 256, 0, s2>>>(p_encw2T, enc_w2, EMBD, EMBD);
        n = (long)512*EMBD;
        prep_postEmbT_k<<<(unsigned)((n+255)/256), 256, 0, s2>>>(post_w);

        for (int cchunk = 0; cchunk < NCH; cchunk++) {
            int t0 = cchunk * SC;
            int nsteps = (t0 + SC <= TS) ? SC : (TS - t0);
            int M = nsteps * BB;                       // 4096 or 3840 (both %128==0)
            size_t ro = (size_t)t0 * BB;
            run128_s(s2, p_obsb + ro*OBSD, OBSD, p_encw1T, OBSD,
                     p_embh + ro*EMBD, EMBD, enc_b1, M, EMBD, OBSD, 1, 1);
            run128_s(s2, p_embh + ro*EMBD, EMBD, p_encw2T, EMBD,
                     p_emb + ro*EMBD, EMBD, enc_b2, M, EMBD, EMBD, 1, 1);
            run128_s(s2, p_emb + ro*EMBD, EMBD, p_postEmbT, EMBD,
                     p_post_emb + ro*512, 512, post_b, M, 512, EMBD, 0, 0);
            cudaEventRecord(evPE[cchunk], s2);
        }
        // Phase-C weights (needed only after join)
        n = (long)OBSD*EMBD;
        transpose_bf_k<<<(unsigned)((n+255)/256), 256, 0, s2>>>(p_decw2T, dec_w2, EMBD, OBSD);
        n = (long)2048*FEATD;
        prep_w1fT_k<<<(unsigned)((n+255)/256), 256, 0, s2>>>(dec_w1, dec_b1, rew_w1, rew_b1);
        cudaEventRecord(evSide, s2);
    }

    // ---- main stream: Phase-B weight prep ----
    cudaMemsetAsync(p_h, 0, (size_t)BB*DETD*sizeof(bf16));
    {
        long n;
        n = (long)3*DETD*KIH;
        prep_wihP_k<<<(unsigned)((n+255)/256), 256>>>(gru_wih);
        n = (long)SN*DETD;
        prep_whT_k<<<(unsigned)((n+255)/256), 256>>>(prior_w, prior_b, post_w, gru_whh, gru_bhh);
    }

    // ---- Phase B: sequential recurrence (waits per post_emb chunk) ----
    for (int t = 0; t < TS; t++) {
        if ((t % SC) == 0) cudaStreamWaitEvent(0, evPE[t / SC], 0);
        float* S_t = p_S_all + (size_t)t*BB*SN;
        run64_s(0, p_h, DETD, p_WhT, DETD, S_t, SN, p_bh, BB, SN, DETD, 0, 0);
        gzgru_k<<<dim3(8, 8), 256, SMEMGZ>>>(
            S_t,
            p_post_emb + (size_t)t*BB*512,
            eps + (size_t)t*BB*STOD,
            actions + (size_t)t*BB*ACTD,
            p_wihP, gru_bih,
            dones + (size_t)t*BB,
            p_feat + (size_t)t*BB*FEATD);
    }

    // ---- join side stream, then Phase C ----
    cudaStreamWaitEvent(0, evSide, 0);
    klbatch_k<<<RR, STOD>>>();
    run128_s(0, p_feat, FEATD, p_W1fT, FEATD, p_H1, 2048, p_b1f, RR, 2048, FEATD, 1, 1);
    run128_s(0, p_H1, 2048, p_decw2T, EMBD, p_pred, OBSD, dec_b2, RR, OBSD, EMBD, 0, 0);
    recon_k<<<RR, 128>>>(obs);
    rew_k<<<RR, 256>>>(rewards, rew_w2, rew_b2);
    final_k<<<1, 256>>>(out);

    (void)in_sizes; (void)n_in; (void)out_size;
}